// round 16
// baseline (speedup 1.0000x reference)
#include <cuda_runtime.h>

#define N_NEURONS 6
#define STEPS 10
#define SUBSTEPS 8
#define A_P 0.02f
#define B_P 0.2f
#define C_P (-65.0f)
#define D_P 8.0f
#define I_TONIC (-1.0f)
#define SYNTH 0.05f
#define SUPPR 0.1f
#define EMA_ALPHA 0.05f
#define RATE_DECAY 0.95f
#define PC_DT 0.1f

// tanh via MUFU.EX2 + fast divide: err ~1e-6, no branches, short latency
__device__ __forceinline__ float ftanh(float x) {
    float e = __expf(2.0f * x);
    return 1.0f - __fdividef(2.0f, e + 1.0f);
}

// sum within groups of 8 lanes
__device__ __forceinline__ float sum8(float x) {
    x += __shfl_xor_sync(0xFFFFFFFFu, x, 4);
    x += __shfl_xor_sync(0xFFFFFFFFu, x, 2);
    x += __shfl_xor_sync(0xFFFFFFFFu, x, 1);
    return x;
}

__global__ void __launch_bounds__(32, 1) spiking_pineal_kernel(
    const float* __restrict__ light_level,
    const float* __restrict__ retinal_luminance,
    const float* __restrict__ melatonin_raw,
    const float* __restrict__ mel_ema,
    const float* __restrict__ v_in,
    const float* __restrict__ u_in,
    const float* __restrict__ rate_in,
    const float* __restrict__ noise,      // [STEPS, N_NEURONS]
    const float* __restrict__ vs_in,      // [2,4]
    const float* __restrict__ va_in,      // [2,4]
    const float* __restrict__ prec_in,    // [2,4]
    float* __restrict__ out)              // [7]
{
    const int lane = threadIdx.x & 31;
    const int grp  = lane >> 3;          // 0..3: which reduction this group owns
    const int sub  = lane & 7;           // 0..7: PC cell index (distinct per group)
    const int li   = sub < N_NEURONS ? sub : N_NEURONS - 1;  // clamped neuron idx

    // ---- issue ALL loads up front (independent, max MLP; one DRAM trip) ----
    const float ll   = *light_level;
    const float rl   = *retinal_luminance;
    const float mraw = *melatonin_raw;
    const float mema = *mel_ema;

    float v    = v_in[li];
    float u    = u_in[li];
    const float rate0 = rate_in[li];

    float nz[STEPS];
    #pragma unroll
    for (int s = 0; s < STEPS; s++)
        nz[s] = noise[s * N_NEURONS + li];

    float vs0  = vs_in[sub];
    float va0  = va_in[sub];
    float prec = prec_in[sub];

    // ---- scalar chemistry ----
    const float light   = fminf(1.0f, ll * 0.6f + rl * 0.4f);
    const float mel_sup = fmaxf(0.0f, mraw - SUPPR * light);
    const float mel_syn = fminf(1.0f, mraw + SYNTH * (1.0f - light));
    const float mel     = (light > 0.3f) ? mel_sup : mel_syn;
    const float ema     = mema + EMA_ALPHA * (mel - mema);

    // early outputs: store-only predicated bodies, STG drain overlaps recurrences
    if (lane == 0) out[0] = light;
    if (lane == 1) out[1] = mel;
    if (lane == 2) out[2] = ema;

    // per-neuron injected current (selects, branchless)
    float I =
        (sub == 0) ? light * 15.0f :
        (sub == 1) ? light * 10.0f :
        (sub == 2) ? (1.0f - light) * 8.0f :
        (sub == 3) ? mel * 12.0f :
        (sub == 4) ? mel * 8.0f :
                     (1.0f - mel) * 6.0f;
    const float Ibase = I + I_TONIC;

    // ---- Izhikevich, 10 serial steps ----
    // Loop body carries only (v, u). Per-step critical chain:
    //   FFMA(0.04,v,6) -> FFMA(v,·,K) -> FSETP(data) -> FSEL  = 16 cy.
    // spk saved per step; rate folded in closed form afterwards.
    float spks[STEPS];
    #pragma unroll
    for (int s = 0; s < STEPS; s++) {
        const float I_in = fmaf(nz[s], 0.3f, Ibase);
        const float v2 = fmaf(v, fmaf(0.04f, v, 6.0f), 140.0f - u + I_in);
        const float u2 = fmaf(A_P, fmaf(B_P, v, -u), u);
        const bool fired = (v2 >= 30.0f);
        const float spk = fired ? 1.0f : 0.0f;
        v = fired ? C_P : v2;
        u = fmaf(D_P, spk, u2);
        spks[s] = spk;
    }

    // rate_10 = 0.95^10 * rate0 + 0.05 * sum_s 0.95^(9-s) * spk_s  (balanced tree)
    const float d95[10] = {1.0f, 0.95f, 0.9025f, 0.857375f, 0.81450625f,
                           0.7737809375f, 0.735091890625f, 0.69833729609375f,
                           0.6634204312890625f, 0.630249409724609f};
    const float r01 = d95[9] * spks[0] + d95[8] * spks[1];
    const float r23 = d95[7] * spks[2] + d95[6] * spks[3];
    const float r45 = d95[5] * spks[4] + d95[4] * spks[5];
    const float r67 = d95[3] * spks[6] + d95[2] * spks[7];
    const float r89 = d95[1] * spks[8] + d95[0] * spks[9];
    const float spk_wsum = ((r01 + r23) + (r45 + r67)) + r89;
    const float rate = fmaf(0.5987369392383787f, rate0, 0.05f * spk_wsum); // 0.95^10

    // ---- predictive-coding column, closed form ----
    // va_t = pred + 0.9^t (va0 - pred)
    // vs_8 = 0.9^8 vs0 + 0.1 sens * S8 + 0.05 * sum_t 0.9^(7-t) tanh(va_t)
    const int ch = (sub >> 2);
    const float sens = (ch == 0) ? light : mel;
    const float pred = (ch == 0) ? light : ema;

    const float p9[9] = {1.0f, 0.9f, 0.81f, 0.729f, 0.6561f, 0.59049f,
                         0.531441f, 0.4782969f, 0.43046721f};
    const float dva = va0 - pred;

    // 8 independent tanh evaluations (MUFU pipelined), weight applied inline
    float w[SUBSTEPS];
    #pragma unroll
    for (int t = 0; t < SUBSTEPS; t++)
        w[t] = p9[7 - t] * ftanh(fmaf(p9[t], dva, pred));

    // balanced-tree sum (depth 3)
    const float s01 = w[0] + w[1], s23 = w[2] + w[3];
    const float s45 = w[4] + w[5], s67 = w[6] + w[7];
    const float wsum = (s01 + s23) + (s45 + s67);

    const float S8 = (1.0f - 0.43046721f) / 0.1f;  // sum_{t=0..7} 0.9^t
    const float vs = fmaf(0.43046721f, vs0,
                     fmaf(0.1f * S8, sens, 0.05f * wsum));

    const float pe = sens - ftanh(vs);
    const float pe2 = pe * pe;
    const float prec_new = fmaf(0.1f, __fdividef(1.0f, 1.0f + pe2) - prec, prec);

    // ---- ONE reduction per 8-lane group (3 shuffles per lane total) ----
    // grp0 -> mean|pe|, grp1 -> mean prec, grp2 -> free energy, grp3 -> mean rate
    const float pe_c = fabsf(pe) * 0.125f;
    const float pr_c = prec_new * 0.125f;
    const float fe_c = prec_new * pe2 * 0.5f;
    const float r_c  = (sub < N_NEURONS) ? rate * (1.0f / (float)N_NEURONS) : 0.0f;

    const float contrib =
        (grp == 0) ? pe_c :
        (grp == 1) ? pr_c :
        (grp == 2) ? fe_c : r_c;

    const float result = sum8(contrib);

    // lanes 0, 8, 16, 24 each store one scalar — predicated, no gather
    if (sub == 0)
        out[3 + grp] = result;
}

extern "C" void kernel_launch(void* const* d_in, const int* in_sizes, int n_in,
                              void* d_out, int out_size) {
    (void)in_sizes; (void)n_in; (void)out_size;
    spiking_pineal_kernel<<<1, 32>>>(
        (const float*)d_in[0],   // light_level
        (const float*)d_in[1],   // retinal_luminance
        (const float*)d_in[2],   // melatonin_raw
        (const float*)d_in[3],   // mel_ema
        (const float*)d_in[4],   // v
        (const float*)d_in[5],   // u
        (const float*)d_in[6],   // rate
        (const float*)d_in[7],   // noise
        (const float*)d_in[8],   // v_soma
        (const float*)d_in[9],   // v_apical
        (const float*)d_in[10],  // precision
        (float*)d_out);
}

// round 17
// speedup vs baseline: 1.0594x; 1.0594x over previous
#include <cuda_runtime.h>

#define N_NEURONS 6
#define STEPS 10
#define SUBSTEPS 8
#define A_P 0.02f
#define B_P 0.2f
#define C_P (-65.0f)
#define D_P 8.0f
#define I_TONIC (-1.0f)
#define SYNTH 0.05f
#define SUPPR 0.1f
#define EMA_ALPHA 0.05f
#define RATE_DECAY 0.95f
#define PC_DT 0.1f

// tanh via MUFU.EX2 + fast divide: err ~1e-6, no branches, short latency
__device__ __forceinline__ float ftanh(float x) {
    float e = __expf(2.0f * x);
    return 1.0f - __fdividef(2.0f, e + 1.0f);
}

// sum within groups of 8 lanes
__device__ __forceinline__ float sum8(float x) {
    x += __shfl_xor_sync(0xFFFFFFFFu, x, 4);
    x += __shfl_xor_sync(0xFFFFFFFFu, x, 2);
    x += __shfl_xor_sync(0xFFFFFFFFu, x, 1);
    return x;
}

__global__ void __launch_bounds__(32, 1) spiking_pineal_kernel(
    const float* __restrict__ light_level,
    const float* __restrict__ retinal_luminance,
    const float* __restrict__ melatonin_raw,
    const float* __restrict__ mel_ema,
    const float* __restrict__ v_in,
    const float* __restrict__ u_in,
    const float* __restrict__ rate_in,
    const float* __restrict__ noise,      // [STEPS, N_NEURONS]
    const float* __restrict__ vs_in,      // [2,4]
    const float* __restrict__ va_in,      // [2,4]
    const float* __restrict__ prec_in,    // [2,4]
    float* __restrict__ out)              // [7]
{
    const int lane = threadIdx.x & 31;
    const int grp  = lane >> 3;          // 0..3: which reduction this group owns
    const int sub  = lane & 7;           // 0..7: PC cell index (distinct per group)
    const int li   = sub < N_NEURONS ? sub : N_NEURONS - 1;  // clamped neuron idx

    // ---- issue ALL loads up front (independent, max MLP; one DRAM trip) ----
    const float ll   = *light_level;
    const float rl   = *retinal_luminance;
    const float mraw = *melatonin_raw;
    const float mema = *mel_ema;

    float v    = v_in[li];
    float u    = u_in[li];
    const float rate0 = rate_in[li];

    float nz[STEPS];
    #pragma unroll
    for (int s = 0; s < STEPS; s++)
        nz[s] = noise[s * N_NEURONS + li];

    float vs0  = vs_in[sub];
    float va0  = va_in[sub];
    float prec = prec_in[sub];

    // ---- scalar chemistry ----
    const float light   = fminf(1.0f, ll * 0.6f + rl * 0.4f);
    const float mel_sup = fmaxf(0.0f, mraw - SUPPR * light);
    const float mel_syn = fminf(1.0f, mraw + SYNTH * (1.0f - light));
    const float mel     = (light > 0.3f) ? mel_sup : mel_syn;
    const float ema     = mema + EMA_ALPHA * (mel - mema);

    // early outputs: store-only predicated bodies, STG drain overlaps recurrences
    if (lane == 0) out[0] = light;
    if (lane == 1) out[1] = mel;
    if (lane == 2) out[2] = ema;

    // per-neuron injected current (selects, branchless)
    float I =
        (sub == 0) ? light * 15.0f :
        (sub == 1) ? light * 10.0f :
        (sub == 2) ? (1.0f - light) * 8.0f :
        (sub == 3) ? mel * 12.0f :
        (sub == 4) ? mel * 8.0f :
                     (1.0f - mel) * 6.0f;
    const float Ibase = I + I_TONIC;

    // ---- Izhikevich, 10 serial steps ----
    // Loop body carries only (v, u). Per-step critical chain:
    //   FFMA(0.04,v,6) -> FFMA(v,·,K) -> FSETP(data) -> FSEL  = 16 cy.
    // spk saved per step; rate folded in closed form afterwards.
    float spks[STEPS];
    #pragma unroll
    for (int s = 0; s < STEPS; s++) {
        const float I_in = fmaf(nz[s], 0.3f, Ibase);
        const float v2 = fmaf(v, fmaf(0.04f, v, 6.0f), 140.0f - u + I_in);
        const float u2 = fmaf(A_P, fmaf(B_P, v, -u), u);
        const bool fired = (v2 >= 30.0f);
        const float spk = fired ? 1.0f : 0.0f;
        v = fired ? C_P : v2;
        u = fmaf(D_P, spk, u2);
        spks[s] = spk;
    }

    // rate_10 = 0.95^10 * rate0 + 0.05 * sum_s 0.95^(9-s) * spk_s  (balanced tree)
    const float d95[10] = {1.0f, 0.95f, 0.9025f, 0.857375f, 0.81450625f,
                           0.7737809375f, 0.735091890625f, 0.69833729609375f,
                           0.6634204312890625f, 0.630249409724609f};
    const float r01 = d95[9] * spks[0] + d95[8] * spks[1];
    const float r23 = d95[7] * spks[2] + d95[6] * spks[3];
    const float r45 = d95[5] * spks[4] + d95[4] * spks[5];
    const float r67 = d95[3] * spks[6] + d95[2] * spks[7];
    const float r89 = d95[1] * spks[8] + d95[0] * spks[9];
    const float spk_wsum = ((r01 + r23) + (r45 + r67)) + r89;
    const float rate = fmaf(0.5987369392383787f, rate0, 0.05f * spk_wsum); // 0.95^10

    // ---- predictive-coding column, closed form ----
    // va_t = pred + 0.9^t (va0 - pred)
    // vs_8 = 0.9^8 vs0 + 0.1 sens * S8 + 0.05 * sum_t 0.9^(7-t) tanh(va_t)
    const int ch = (sub >> 2);
    const float sens = (ch == 0) ? light : mel;
    const float pred = (ch == 0) ? light : ema;

    const float p9[9] = {1.0f, 0.9f, 0.81f, 0.729f, 0.6561f, 0.59049f,
                         0.531441f, 0.4782969f, 0.43046721f};
    const float dva = va0 - pred;

    // 8 independent tanh evaluations (MUFU pipelined), weight applied inline
    float w[SUBSTEPS];
    #pragma unroll
    for (int t = 0; t < SUBSTEPS; t++)
        w[t] = p9[7 - t] * ftanh(fmaf(p9[t], dva, pred));

    // balanced-tree sum (depth 3)
    const float s01 = w[0] + w[1], s23 = w[2] + w[3];
    const float s45 = w[4] + w[5], s67 = w[6] + w[7];
    const float wsum = (s01 + s23) + (s45 + s67);

    const float S8 = (1.0f - 0.43046721f) / 0.1f;  // sum_{t=0..7} 0.9^t
    const float vs = fmaf(0.43046721f, vs0,
                     fmaf(0.1f * S8, sens, 0.05f * wsum));

    const float pe = sens - ftanh(vs);
    const float pe2 = pe * pe;
    const float prec_new = fmaf(0.1f, __fdividef(1.0f, 1.0f + pe2) - prec, prec);

    // ---- ONE reduction per 8-lane group (3 shuffles per lane total) ----
    // grp0 -> mean|pe|, grp1 -> mean prec, grp2 -> free energy, grp3 -> mean rate
    const float pe_c = fabsf(pe) * 0.125f;
    const float pr_c = prec_new * 0.125f;
    const float fe_c = prec_new * pe2 * 0.5f;
    const float r_c  = (sub < N_NEURONS) ? rate * (1.0f / (float)N_NEURONS) : 0.0f;

    const float contrib =
        (grp == 0) ? pe_c :
        (grp == 1) ? pr_c :
        (grp == 2) ? fe_c : r_c;

    const float result = sum8(contrib);

    // lanes 0, 8, 16, 24 each store one scalar — predicated, no gather
    if (sub == 0)
        out[3 + grp] = result;
}

extern "C" void kernel_launch(void* const* d_in, const int* in_sizes, int n_in,
                              void* d_out, int out_size) {
    (void)in_sizes; (void)n_in; (void)out_size;
    spiking_pineal_kernel<<<1, 32>>>(
        (const float*)d_in[0],   // light_level
        (const float*)d_in[1],   // retinal_luminance
        (const float*)d_in[2],   // melatonin_raw
        (const float*)d_in[3],   // mel_ema
        (const float*)d_in[4],   // v
        (const float*)d_in[5],   // u
        (const float*)d_in[6],   // rate
        (const float*)d_in[7],   // noise
        (const float*)d_in[8],   // v_soma
        (const float*)d_in[9],   // v_apical
        (const float*)d_in[10],  // precision
        (float*)d_out);
}